// round 3
// baseline (speedup 1.0000x reference)
#include <cuda_runtime.h>

#define NN 100000
#define EE 800000
#define ET (EE + NN)
#define GG 256
#define FD 128

// ------------------------- scratch (static device globals; no allocs) ------
__device__ float g_hpA[(size_t)NN * FD];   // GEMM output (per-layer transformed feats)
__device__ float g_hpB[(size_t)NN * FD];   // aggregate output (layer output)
__device__ float g_als[NN * 4];
__device__ float g_ald[NN * 4];
__device__ int   g_deg[NN];
__device__ int   g_rowptr[NN + 1];
__device__ int   g_cursor[NN];
__device__ int   g_csr[ET];
__device__ int   g_bsum[128];

// ----------------------- packed f32x2 helpers (sm_103a) -------------------
__device__ __forceinline__ unsigned long long pk2(float a, float b) {
    unsigned long long r;
    asm("mov.b64 %0, {%1, %2};" : "=l"(r) : "f"(a), "f"(b));
    return r;
}
__device__ __forceinline__ void upk2(unsigned long long v, float& a, float& b) {
    asm("mov.b64 {%0, %1}, %2;" : "=f"(a), "=f"(b) : "l"(v));
}
__device__ __forceinline__ unsigned long long ffma2(unsigned long long a,
                                                    unsigned long long b,
                                                    unsigned long long c) {
    unsigned long long r;
    asm("fma.rn.f32x2 %0, %1, %2, %3;" : "=l"(r) : "l"(a), "l"(b), "l"(c));
    return r;
}

// ------------------------------ CSR build ---------------------------------
__global__ void k_deg_init() {
    int i = blockIdx.x * blockDim.x + threadIdx.x;
    if (i < NN) g_deg[i] = 1;   // self-loop pre-counted
}

__global__ void k_count(const int* __restrict__ ei) {
    int e = blockIdx.x * blockDim.x + threadIdx.x;
    if (e < EE) atomicAdd(&g_deg[ei[EE + e]], 1);   // ei row 1 = dst
}

__global__ void k_scan1() {
    __shared__ int sh[1024];
    int tid = threadIdx.x;
    int i = blockIdx.x * 1024 + tid;
    int v = (i < NN) ? g_deg[i] : 0;
    sh[tid] = v;
    __syncthreads();
#pragma unroll
    for (int off = 1; off < 1024; off <<= 1) {
        int t = (tid >= off) ? sh[tid - off] : 0;
        __syncthreads();
        sh[tid] += t;
        __syncthreads();
    }
    if (i < NN) g_rowptr[i] = sh[tid] - v;          // exclusive
    if (tid == 1023) g_bsum[blockIdx.x] = sh[tid];  // block total
}

__global__ void k_scan2(int nb) {
    __shared__ int sh[128];
    int tid = threadIdx.x;
    sh[tid] = (tid < nb) ? g_bsum[tid] : 0;
    __syncthreads();
    if (tid == 0) {
        int run = 0;
        for (int i = 0; i < nb; i++) { int t = sh[i]; sh[i] = run; run += t; }
    }
    __syncthreads();
    if (tid < nb) g_bsum[tid] = sh[tid];
}

__global__ void k_scan3() {
    int i = blockIdx.x * blockDim.x + threadIdx.x;
    if (i < NN) {
        int r = g_rowptr[i] + g_bsum[i >> 10];
        g_rowptr[i] = r;
        g_cursor[i] = r;
    }
    if (i == 0) g_rowptr[NN] = ET;
}

__global__ void k_fill(const int* __restrict__ ei) {
    int t = blockIdx.x * blockDim.x + threadIdx.x;
    if (t < EE) {
        int s = ei[t], d = ei[EE + t];
        int slot = atomicAdd(&g_cursor[d], 1);
        g_csr[slot] = s;
    } else if (t < ET) {
        int n = t - EE;
        int slot = atomicAdd(&g_cursor[n], 1);
        g_csr[slot] = n;
    }
}

// make per-segment order deterministic (atomics fill in arbitrary order)
__global__ void k_sortseg() {
    int n = blockIdx.x * blockDim.x + threadIdx.x;
    if (n >= NN) return;
    int b = g_rowptr[n], e = g_rowptr[n + 1];
    for (int i = b + 1; i < e; i++) {
        int v = g_csr[i];
        int j = i - 1;
        while (j >= b && g_csr[j] > v) { g_csr[j + 1] = g_csr[j]; j--; }
        g_csr[j + 1] = v;
    }
}

// ------------------- GEMM: hp = A @ W^T  (+ fused logits) -----------------
// A: [NN, K], W: [128, K] row-major, hp: [NN, 128] (written to g_hpA)
// also writes g_als[n][h] = dot(hp[n, h*32:...], a_src[h]), same for a_dst.
// inner loop uses packed fma.rn.f32x2 (FFMA2): rows packed in pairs.
template <int K>
__global__ void __launch_bounds__(256)
k_gemm(const float* __restrict__ Aext,
       const float* __restrict__ W,
       const float* __restrict__ asrc,
       const float* __restrict__ adst,
       int useExt) {
    __shared__ float sh_w[32][132];  // [kk][c], padded: conflict-free LDS.128
    __shared__ float sh_h[32][72];   // [kk][r], padded (72*4=288B, 16B-aligned rows)

    const float* __restrict__ A = useExt ? Aext : g_hpB;
    int tid = threadIdx.x;
    int tx = tid & 31, ty = tid >> 5;   // lane == tx (warp = fixed ty)
    int row0 = blockIdx.x * 64;

    // acc2[rp][c]: row-pair rp (rows ty*8+2rp, +2rp+1), col tx*4+c, packed f32x2
    unsigned long long acc2[4][4];
#pragma unroll
    for (int i = 0; i < 4; i++)
#pragma unroll
        for (int j = 0; j < 4; j++) acc2[i][j] = 0ull;

    for (int k0 = 0; k0 < K; k0 += 32) {
#pragma unroll
        for (int idx = tid; idx < 4096; idx += 256) {
            int kk = idx & 31, c = idx >> 5;
            sh_w[kk][c] = W[c * K + k0 + kk];
        }
#pragma unroll
        for (int idx = tid; idx < 2048; idx += 256) {
            int kk = idx & 31, r = idx >> 5;
            int row = row0 + r;
            if (row >= NN) row = NN - 1;
            sh_h[kk][r] = A[(size_t)row * K + k0 + kk];
        }
        __syncthreads();
#pragma unroll
        for (int kk = 0; kk < 32; kk++) {
            float4 w4 = *(const float4*)&sh_w[kk][tx * 4];
            unsigned long long wp[4] = {pk2(w4.x, w4.x), pk2(w4.y, w4.y),
                                        pk2(w4.z, w4.z), pk2(w4.w, w4.w)};
            // 8 row values for this warp as 4 packed pairs, straight from smem
            ulonglong2 hp0 = *(const ulonglong2*)&sh_h[kk][ty * 8];
            ulonglong2 hp1 = *(const ulonglong2*)&sh_h[kk][ty * 8 + 4];
            unsigned long long h2[4] = {hp0.x, hp0.y, hp1.x, hp1.y};
#pragma unroll
            for (int rp = 0; rp < 4; rp++) {
                acc2[rp][0] = ffma2(h2[rp], wp[0], acc2[rp][0]);
                acc2[rp][1] = ffma2(h2[rp], wp[1], acc2[rp][1]);
                acc2[rp][2] = ffma2(h2[rp], wp[2], acc2[rp][2]);
                acc2[rp][3] = ffma2(h2[rp], wp[3], acc2[rp][3]);
            }
        }
        __syncthreads();
    }

    // unpack to per-row accumulators
    float acc[8][4];
#pragma unroll
    for (int rp = 0; rp < 4; rp++)
#pragma unroll
        for (int c = 0; c < 4; c++)
            upk2(acc2[rp][c], acc[2 * rp][c], acc[2 * rp + 1][c]);

    // epilogue: store hp rows + fused attention logits (8-lane head groups)
    float4 as4 = *(const float4*)&asrc[tx * 4];
    float4 ad4 = *(const float4*)&adst[tx * 4];
    int h = tx >> 3;
#pragma unroll
    for (int i = 0; i < 8; i++) {
        int row = row0 + ty * 8 + i;
        float ps = acc[i][0] * as4.x + acc[i][1] * as4.y +
                   acc[i][2] * as4.z + acc[i][3] * as4.w;
        float pd = acc[i][0] * ad4.x + acc[i][1] * ad4.y +
                   acc[i][2] * ad4.z + acc[i][3] * ad4.w;
#pragma unroll
        for (int off = 4; off >= 1; off >>= 1) {
            ps += __shfl_xor_sync(0xffffffffu, ps, off);
            pd += __shfl_xor_sync(0xffffffffu, pd, off);
        }
        if (row < NN) {
            *(float4*)&g_hpA[(size_t)row * FD + tx * 4] =
                make_float4(acc[i][0], acc[i][1], acc[i][2], acc[i][3]);
            if ((tx & 7) == 0) {
                g_als[row * 4 + h] = ps;
                g_ald[row * 4 + h] = pd;
            }
        }
    }
}

// ----------- edge-softmax aggregation: one warp per dst node --------------
// two-pass exact softmax:
//   pass 1: per-head max of als over segment (leaky_relu monotone + ald const
//           per segment => m = leaky(max(als) + ald), exactly equal to
//           segment_max(leaky(als+ald)))
//   pass 2: p = exp(leaky(als+ald) - m), computed on 4 lanes (1 MUFU inst per
//           edge per warp) and shfl-broadcast; plain FMA accumulation chain.
__global__ void __launch_bounds__(256)
k_aggregate(const float* __restrict__ bias, int do_relu) {
    int n = (blockIdx.x * blockDim.x + threadIdx.x) >> 5;
    if (n >= NN) return;
    int lane = threadIdx.x & 31;
    int h = lane >> 3;                  // head for this lane's 4 feature chans
    int hh = lane & 3;                  // head for pass-1 / exp duty
    int beg = g_rowptr[n], end = g_rowptr[n + 1];

    // ---- pass 1: per-head max of als (8 edge-groups x 4 heads in parallel)
    float mx = -1e30f;
    for (int j = beg + (lane >> 2); j < end; j += 8)
        mx = fmaxf(mx, g_als[g_csr[j] * 4 + hh]);
    mx = fmaxf(mx, __shfl_xor_sync(0xffffffffu, mx, 16));
    mx = fmaxf(mx, __shfl_xor_sync(0xffffffffu, mx, 8));
    mx = fmaxf(mx, __shfl_xor_sync(0xffffffffu, mx, 4));
    // every lane now holds max(als) for head hh
    float adh = g_ald[n * 4 + hh];
    float mh = mx + adh;
    mh = (mh > 0.f) ? mh : 0.2f * mh;   // m for head hh

    // ---- pass 2: accumulate
    float s = 0.f, ax = 0.f, ay = 0.f, az = 0.f, aw = 0.f;
#pragma unroll 2
    for (int j = beg; j < end; j++) {
        int src = g_csr[j];
        float p = 0.f;
        if (lane < 4) {
            float e = g_als[src * 4 + lane] + adh;   // lane<4: hh==lane
            e = (e > 0.f) ? e : 0.2f * e;
            p = __expf(e - mh);
        }
        p = __shfl_sync(0xffffffffu, p, h);
        float4 v = *(const float4*)&g_hpA[(size_t)src * FD + lane * 4];
        ax = fmaf(p, v.x, ax);
        ay = fmaf(p, v.y, ay);
        az = fmaf(p, v.z, az);
        aw = fmaf(p, v.w, aw);
        s += p;
    }
    float inv = 1.f / (s + 1e-16f);
    float4 b4 = *(const float4*)&bias[lane * 4];
    float ox = fmaf(ax, inv, b4.x);
    float oy = fmaf(ay, inv, b4.y);
    float oz = fmaf(az, inv, b4.z);
    float ow = fmaf(aw, inv, b4.w);
    if (do_relu) {
        ox = fmaxf(ox, 0.f); oy = fmaxf(oy, 0.f);
        oz = fmaxf(oz, 0.f); ow = fmaxf(ow, 0.f);
    }
    *(float4*)&g_hpB[(size_t)n * FD + lane * 4] = make_float4(ox, oy, oz, ow);
}

// -------------------- global mean pool (batch is sorted) ------------------
__device__ __forceinline__ int lowbound(const int* __restrict__ a, int n, int key) {
    int lo = 0, hi = n;
    while (lo < hi) {
        int mid = (lo + hi) >> 1;
        if (a[mid] < key) lo = mid + 1; else hi = mid;
    }
    return lo;
}

__global__ void k_pool(const int* __restrict__ batch, float* __restrict__ out) {
    __shared__ int sb, se;
    int g = blockIdx.x;
    if (threadIdx.x == 0) {
        sb = lowbound(batch, NN, g);
        se = lowbound(batch, NN, g + 1);
    }
    __syncthreads();
    int b = sb, e = se;
    float acc = 0.f;
    for (int nidx = b; nidx < e; nidx++)
        acc += g_hpB[(size_t)nidx * FD + threadIdx.x];
    float c = (float)(e - b);
    out[g * FD + threadIdx.x] = acc / fmaxf(c, 1.f);
}

// ------------------------------- driver -----------------------------------
extern "C" void kernel_launch(void* const* d_in, const int* in_sizes, int n_in,
                              void* d_out, int out_size) {
    const float* x     = (const float*)d_in[0];
    const int*   ei    = (const int*)d_in[1];
    // d_in[2] = edge_weight (unused by reference)
    const int*   batch = (const int*)d_in[3];
    const float* W0 = (const float*)d_in[4];
    const float* as0 = (const float*)d_in[5];
    const float* ad0 = (const float*)d_in[6];
    const float* b0 = (const float*)d_in[7];
    const float* W1 = (const float*)d_in[8];
    const float* as1 = (const float*)d_in[9];
    const float* ad1 = (const float*)d_in[10];
    const float* b1 = (const float*)d_in[11];
    const float* W2 = (const float*)d_in[12];
    const float* as2 = (const float*)d_in[13];
    const float* ad2 = (const float*)d_in[14];
    const float* b2 = (const float*)d_in[15];
    float* out = (float*)d_out;

    // --- CSR build (shared by all 3 layers) ---
    k_deg_init<<<(NN + 255) / 256, 256>>>();
    k_count<<<(EE + 255) / 256, 256>>>(ei);
    k_scan1<<<(NN + 1023) / 1024, 1024>>>();
    k_scan2<<<1, 128>>>((NN + 1023) / 1024);
    k_scan3<<<(NN + 255) / 256, 256>>>();
    k_fill<<<(ET + 255) / 256, 256>>>(ei);
    k_sortseg<<<(NN + 255) / 256, 256>>>();

    const int GEMM_GRID = (NN + 63) / 64;         // 1563
    const int AGG_GRID  = (NN * 32 + 255) / 256;  // 12500

    // layer 0: x(64) -> hpA -> aggregate(+b0, relu) -> hpB
    k_gemm<64><<<GEMM_GRID, 256>>>(x, W0, as0, ad0, 1);
    k_aggregate<<<AGG_GRID, 256>>>(b0, 1);
    // layer 1: hpB(128) -> hpA -> aggregate(+b1, relu) -> hpB
    k_gemm<128><<<GEMM_GRID, 256>>>(nullptr, W1, as1, ad1, 0);
    k_aggregate<<<AGG_GRID, 256>>>(b1, 1);
    // layer 2: hpB(128) -> hpA -> aggregate(+b2, no relu) -> hpB
    k_gemm<128><<<GEMM_GRID, 256>>>(nullptr, W2, as2, ad2, 0);
    k_aggregate<<<AGG_GRID, 256>>>(b2, 0);

    // global mean pool
    k_pool<<<GG, FD>>>(batch, out);
}

// round 4
// speedup vs baseline: 1.0702x; 1.0702x over previous
#include <cuda_runtime.h>

#define NN 100000
#define EE 800000
#define ET (EE + NN)
#define GG 256
#define FD 128

// ------------------------- scratch (static device globals; no allocs) ------
__device__ float g_hpA[(size_t)NN * FD];   // GEMM output (per-layer transformed feats)
__device__ float g_hpB[(size_t)NN * FD];   // aggregate output (layer output)
__device__ float g_als[NN * 4];
__device__ float g_ald[NN * 4];
__device__ int   g_deg[NN];
__device__ int   g_rowptr[NN + 1];
__device__ int   g_cursor[NN];
__device__ int   g_csr[ET];
__device__ int   g_bsum[128];

// ------------------------------ CSR build ---------------------------------
__global__ void k_deg_init() {
    int i = blockIdx.x * blockDim.x + threadIdx.x;
    if (i < NN) g_deg[i] = 1;   // self-loop pre-counted
}

__global__ void k_count(const int* __restrict__ ei) {
    int e = blockIdx.x * blockDim.x + threadIdx.x;
    if (e < EE) atomicAdd(&g_deg[ei[EE + e]], 1);   // ei row 1 = dst
}

__global__ void k_scan1() {
    __shared__ int sh[1024];
    int tid = threadIdx.x;
    int i = blockIdx.x * 1024 + tid;
    int v = (i < NN) ? g_deg[i] : 0;
    sh[tid] = v;
    __syncthreads();
#pragma unroll
    for (int off = 1; off < 1024; off <<= 1) {
        int t = (tid >= off) ? sh[tid - off] : 0;
        __syncthreads();
        sh[tid] += t;
        __syncthreads();
    }
    if (i < NN) g_rowptr[i] = sh[tid] - v;          // exclusive
    if (tid == 1023) g_bsum[blockIdx.x] = sh[tid];  // block total
}

__global__ void k_scan2(int nb) {
    __shared__ int sh[128];
    int tid = threadIdx.x;
    sh[tid] = (tid < nb) ? g_bsum[tid] : 0;
    __syncthreads();
    if (tid == 0) {
        int run = 0;
        for (int i = 0; i < nb; i++) { int t = sh[i]; sh[i] = run; run += t; }
    }
    __syncthreads();
    if (tid < nb) g_bsum[tid] = sh[tid];
}

__global__ void k_scan3() {
    int i = blockIdx.x * blockDim.x + threadIdx.x;
    if (i < NN) {
        int r = g_rowptr[i] + g_bsum[i >> 10];
        g_rowptr[i] = r;
        g_cursor[i] = r;
    }
    if (i == 0) g_rowptr[NN] = ET;
}

__global__ void k_fill(const int* __restrict__ ei) {
    int t = blockIdx.x * blockDim.x + threadIdx.x;
    if (t < EE) {
        int s = ei[t], d = ei[EE + t];
        int slot = atomicAdd(&g_cursor[d], 1);
        g_csr[slot] = s;
    } else if (t < ET) {
        int n = t - EE;
        int slot = atomicAdd(&g_cursor[n], 1);
        g_csr[slot] = n;
    }
}

// make per-segment order deterministic (atomics fill in arbitrary order)
__global__ void k_sortseg() {
    int n = blockIdx.x * blockDim.x + threadIdx.x;
    if (n >= NN) return;
    int b = g_rowptr[n], e = g_rowptr[n + 1];
    for (int i = b + 1; i < e; i++) {
        int v = g_csr[i];
        int j = i - 1;
        while (j >= b && g_csr[j] > v) { g_csr[j + 1] = g_csr[j]; j--; }
        g_csr[j + 1] = v;
    }
}

// ------------------- GEMM: hp = A @ W^T  (+ fused logits) -----------------
// A: [NN, K], W: [128, K] row-major, hp: [NN, 128] (written to g_hpA)
// also writes g_als[n][h] = dot(hp[n, h*32:...], a_src[h]), same for a_dst.
// scalar-FFMA version (R1, known good).
template <int K>
__global__ void __launch_bounds__(256)
k_gemm(const float* __restrict__ Aext,
       const float* __restrict__ W,
       const float* __restrict__ asrc,
       const float* __restrict__ adst,
       int useExt) {
    __shared__ float sh_w[32][132];  // [kk][c], padded: conflict-free LDS.128
    __shared__ float sh_h[32][68];   // [kk][r], padded: 16B-aligned rows

    const float* __restrict__ A = useExt ? Aext : g_hpB;
    int tid = threadIdx.x;
    int tx = tid & 31, ty = tid >> 5;   // lane == tx (warp = fixed ty)
    int row0 = blockIdx.x * 64;

    float acc[8][4];
#pragma unroll
    for (int i = 0; i < 8; i++)
#pragma unroll
        for (int j = 0; j < 4; j++) acc[i][j] = 0.f;

    for (int k0 = 0; k0 < K; k0 += 32) {
#pragma unroll
        for (int idx = tid; idx < 4096; idx += 256) {
            int kk = idx & 31, c = idx >> 5;
            sh_w[kk][c] = W[c * K + k0 + kk];
        }
#pragma unroll
        for (int idx = tid; idx < 2048; idx += 256) {
            int kk = idx & 31, r = idx >> 5;
            int row = row0 + r;
            if (row >= NN) row = NN - 1;
            sh_h[kk][r] = A[(size_t)row * K + k0 + kk];
        }
        __syncthreads();
#pragma unroll
        for (int kk = 0; kk < 32; kk++) {
            float4 w4 = *(const float4*)&sh_w[kk][tx * 4];
            float4 h0 = *(const float4*)&sh_h[kk][ty * 8];
            float4 h1 = *(const float4*)&sh_h[kk][ty * 8 + 4];
            float hr[8] = {h0.x, h0.y, h0.z, h0.w, h1.x, h1.y, h1.z, h1.w};
#pragma unroll
            for (int i = 0; i < 8; i++) {
                acc[i][0] = fmaf(hr[i], w4.x, acc[i][0]);
                acc[i][1] = fmaf(hr[i], w4.y, acc[i][1]);
                acc[i][2] = fmaf(hr[i], w4.z, acc[i][2]);
                acc[i][3] = fmaf(hr[i], w4.w, acc[i][3]);
            }
        }
        __syncthreads();
    }

    // epilogue: store hp rows + fused attention logits (8-lane head groups)
    float4 as4 = *(const float4*)&asrc[tx * 4];
    float4 ad4 = *(const float4*)&adst[tx * 4];
    int h = tx >> 3;
#pragma unroll
    for (int i = 0; i < 8; i++) {
        int row = row0 + ty * 8 + i;
        float ps = acc[i][0] * as4.x + acc[i][1] * as4.y +
                   acc[i][2] * as4.z + acc[i][3] * as4.w;
        float pd = acc[i][0] * ad4.x + acc[i][1] * ad4.y +
                   acc[i][2] * ad4.z + acc[i][3] * ad4.w;
#pragma unroll
        for (int off = 4; off >= 1; off >>= 1) {
            ps += __shfl_xor_sync(0xffffffffu, ps, off);
            pd += __shfl_xor_sync(0xffffffffu, pd, off);
        }
        if (row < NN) {
            *(float4*)&g_hpA[(size_t)row * FD + tx * 4] =
                make_float4(acc[i][0], acc[i][1], acc[i][2], acc[i][3]);
            if ((tx & 7) == 0) {
                g_als[row * 4 + h] = ps;
                g_ald[row * 4 + h] = pd;
            }
        }
    }
}

// ----------- edge-softmax aggregation: one warp per dst node --------------
// two-pass exact softmax, no shuffles in the hot loop:
//   pass 1: per-head max of als over segment (leaky_relu monotone + ald const
//           per segment => m = leaky(max(als) + ald) == segment_max(leaky(.)))
//   pass 2: EVERY lane computes exp for ITS OWN head (h = lane>>3): one MUFU
//           warp-inst per edge (vs two in the online version), no shfl in the
//           dependent chain; plain lat-4 FMA accumulation.
__global__ void __launch_bounds__(256)
k_aggregate(const float* __restrict__ bias, int do_relu) {
    int n = (blockIdx.x * blockDim.x + threadIdx.x) >> 5;
    if (n >= NN) return;
    int lane = threadIdx.x & 31;
    int h = lane >> 3;                  // head for this lane's 4 feature chans
    int hh = lane & 3;                  // head for pass-1 duty
    int beg = g_rowptr[n], end = g_rowptr[n + 1];

    // ---- pass 1: per-head max of als (8 edge-groups x 4 heads in parallel)
    float mx = -1e30f;
    for (int j = beg + (lane >> 2); j < end; j += 8)
        mx = fmaxf(mx, g_als[g_csr[j] * 4 + hh]);
    mx = fmaxf(mx, __shfl_xor_sync(0xffffffffu, mx, 16));
    mx = fmaxf(mx, __shfl_xor_sync(0xffffffffu, mx, 8));
    mx = fmaxf(mx, __shfl_xor_sync(0xffffffffu, mx, 4));
    // lanes 4k..4k+3 hold max for head k; redistribute so each lane has its h
    float mh_own = __shfl_sync(0xffffffffu, mx, h);      // max(als) for head h
    float ad_own = g_ald[n * 4 + h];
    float mh = mh_own + ad_own;
    mh = (mh > 0.f) ? mh : 0.2f * mh;   // segment max logit for this lane's head

    // ---- pass 2: accumulate (each lane self-sufficient; no intra-chain shfl)
    float s = 0.f, ax = 0.f, ay = 0.f, az = 0.f, aw = 0.f;
    for (int j = beg; j < end; j++) {
        int src = g_csr[j];
        float e = g_als[src * 4 + h] + ad_own;
        e = (e > 0.f) ? e : 0.2f * e;
        float p = __expf(e - mh);
        float4 v = *(const float4*)&g_hpA[(size_t)src * FD + lane * 4];
        ax = fmaf(p, v.x, ax);
        ay = fmaf(p, v.y, ay);
        az = fmaf(p, v.z, az);
        aw = fmaf(p, v.w, aw);
        s += p;
    }
    float inv = 1.f / (s + 1e-16f);
    float4 b4 = *(const float4*)&bias[lane * 4];
    float ox = fmaf(ax, inv, b4.x);
    float oy = fmaf(ay, inv, b4.y);
    float oz = fmaf(az, inv, b4.z);
    float ow = fmaf(aw, inv, b4.w);
    if (do_relu) {
        ox = fmaxf(ox, 0.f); oy = fmaxf(oy, 0.f);
        oz = fmaxf(oz, 0.f); ow = fmaxf(ow, 0.f);
    }
    *(float4*)&g_hpB[(size_t)n * FD + lane * 4] = make_float4(ox, oy, oz, ow);
}

// -------------------- global mean pool (batch is sorted) ------------------
__device__ __forceinline__ int lowbound(const int* __restrict__ a, int n, int key) {
    int lo = 0, hi = n;
    while (lo < hi) {
        int mid = (lo + hi) >> 1;
        if (a[mid] < key) lo = mid + 1; else hi = mid;
    }
    return lo;
}

__global__ void k_pool(const int* __restrict__ batch, float* __restrict__ out) {
    __shared__ int sb, se;
    int g = blockIdx.x;
    if (threadIdx.x == 0) {
        sb = lowbound(batch, NN, g);
        se = lowbound(batch, NN, g + 1);
    }
    __syncthreads();
    int b = sb, e = se;
    float acc = 0.f;
    for (int nidx = b; nidx < e; nidx++)
        acc += g_hpB[(size_t)nidx * FD + threadIdx.x];
    float c = (float)(e - b);
    out[g * FD + threadIdx.x] = acc / fmaxf(c, 1.f);
}

// ------------------------------- driver -----------------------------------
extern "C" void kernel_launch(void* const* d_in, const int* in_sizes, int n_in,
                              void* d_out, int out_size) {
    const float* x     = (const float*)d_in[0];
    const int*   ei    = (const int*)d_in[1];
    // d_in[2] = edge_weight (unused by reference)
    const int*   batch = (const int*)d_in[3];
    const float* W0 = (const float*)d_in[4];
    const float* as0 = (const float*)d_in[5];
    const float* ad0 = (const float*)d_in[6];
    const float* b0 = (const float*)d_in[7];
    const float* W1 = (const float*)d_in[8];
    const float* as1 = (const float*)d_in[9];
    const float* ad1 = (const float*)d_in[10];
    const float* b1 = (const float*)d_in[11];
    const float* W2 = (const float*)d_in[12];
    const float* as2 = (const float*)d_in[13];
    const float* ad2 = (const float*)d_in[14];
    const float* b2 = (const float*)d_in[15];
    float* out = (float*)d_out;

    const int GEMM_GRID = (NN + 63) / 64;         // 1563
    const int AGG_GRID  = (NN * 32 + 255) / 256;  // 12500

    // CSR build interleaved with layer-0 GEMM (gemm0 has no CSR dependency).
    // k_gemm<64> is placed at launch index 3 — the slot ncu's -s/-c window
    // captured in previous rounds — to get a profile of the dominant kernel.
    k_deg_init<<<(NN + 255) / 256, 256>>>();
    k_count<<<(EE + 255) / 256, 256>>>(ei);
    k_scan1<<<(NN + 1023) / 1024, 1024>>>();
    k_gemm<64><<<GEMM_GRID, 256>>>(x, W0, as0, ad0, 1);   // launch idx 3
    k_scan2<<<1, 128>>>((NN + 1023) / 1024);
    k_scan3<<<(NN + 255) / 256, 256>>>();
    k_fill<<<(ET + 255) / 256, 256>>>(ei);
    k_sortseg<<<(NN + 255) / 256, 256>>>();

    // layer 0 aggregate (+b0, relu) -> hpB
    k_aggregate<<<AGG_GRID, 256>>>(b0, 1);
    // layer 1: hpB(128) -> hpA -> aggregate(+b1, relu) -> hpB
    k_gemm<128><<<GEMM_GRID, 256>>>(nullptr, W1, as1, ad1, 0);
    k_aggregate<<<AGG_GRID, 256>>>(b1, 1);
    // layer 2: hpB(128) -> hpA -> aggregate(+b2, no relu) -> hpB
    k_gemm<128><<<GEMM_GRID, 256>>>(nullptr, W2, as2, ad2, 0);
    k_aggregate<<<AGG_GRID, 256>>>(b2, 0);

    // global mean pool
    k_pool<<<GG, FD>>>(batch, out);
}